// round 10
// baseline (speedup 1.0000x reference)
#include <cuda_runtime.h>
#include <cstdint>

#define B_     8
#define N_     2048
#define FIN    256
#define FOUT   64
#define LOG2E  1.4426950408889634f
#define ONE_TF 0x3f800000u

// Scratch (device globals: allocation-free rule)
__device__ float    g_WhB[B_ * N_ * FOUT];  // [b][j>>3][o][j&7], tf32-pre-rounded
__device__ float    g_esrc[B_ * N_];        // log2-scaled src logits
__device__ float2   g_edEF[B_ * N_];        // per node: (exp2(d), exp2(0.2 d))
__device__ uint32_t g_bits[B_ * N_ * (N_ / 32)];  // adj bitmask, 4.2 MB (L2-resident)

// ---------------------------------------------------------------------------
// helpers
// ---------------------------------------------------------------------------
__device__ __forceinline__ uint32_t smem_u32(const void* p) {
    uint32_t a;
    asm("{ .reg .u64 t; cvta.to.shared.u64 t, %1; cvt.u32.u64 %0, t; }" : "=r"(a) : "l"(p));
    return a;
}
__device__ __forceinline__ void cpa16(uint32_t dst, const void* src) {
    asm volatile("cp.async.cg.shared.global [%0], [%1], 16;" :: "r"(dst), "l"(src));
}
#define CP_COMMIT() asm volatile("cp.async.commit_group;" ::: "memory")
#define CP_WAIT1()  asm volatile("cp.async.wait_group 1;" ::: "memory")
#define BAR_PAIR(id) asm volatile("bar.sync %0, 64;" :: "r"(id) : "memory")
#define BAR_GEMM()   asm volatile("bar.sync 1, 256;" ::: "memory")  // GEMM warps only

__device__ __forceinline__ float ex2f(float x) {
    float r; asm("ex2.approx.f32 %0, %1;" : "=f"(r) : "f"(x)); return r;
}
__device__ __forceinline__ uint32_t tf32u(float x) {
    uint32_t r; asm("cvt.rn.tf32.f32 %0, %1;" : "=r"(r) : "f"(x)); return r;
}
// D += A*B, m16n8k8 tf32 (base PTX ISA)
#define MMA_TF32(d, a0, a1, a2, a3, b0, b1)                                   \
    asm volatile("mma.sync.aligned.m16n8k8.row.col.f32.tf32.tf32.f32 "        \
                 "{%0,%1,%2,%3}, {%4,%5,%6,%7}, {%8,%9}, {%0,%1,%2,%3};"      \
                 : "+f"((d)[0]), "+f"((d)[1]), "+f"((d)[2]), "+f"((d)[3])     \
                 : "r"(a0), "r"(a1), "r"(a2), "r"(a3), "r"(b0), "r"(b1))

// packed fp32x2 FMA (prep kernel)
#define FMA2(d, a, b) asm("fma.rn.f32x2 %0, %1, %2, %0;" : "+l"(d) : "l"(a), "l"(b))
__device__ __forceinline__ float pair_sum(unsigned long long v) {
    float lo, hi;
    asm("mov.b64 {%0, %1}, %2;" : "=f"(lo), "=f"(hi) : "l"(v));
    return lo + hi;
}
__device__ __forceinline__ unsigned long long pack2(float lo, float hi) {
    unsigned long long r;
    asm("mov.b64 %0, {%1, %2};" : "=l"(r) : "f"(lo), "f"(hi));
    return r;
}

// ---------------------------------------------------------------------------
// Kernel PREP: 512 blocks x 320 threads, WARP-SPECIALIZED.
//   warps 0-7 (t<256): Wh = h@W (FFMA2, W staged per 16KB quarter, h
//     double-buffered cp.async). Named barrier (1,256) so pack warps never
//     participate. Epilogue: g_WhB (tf32, fragment layout), g_esrc, g_edEF.
//   warps 8-9 (t>=256): stream-pack this block's 2048 adj bit-words
//     (256KB -> 8KB), MLP=16, concurrent with the GEMM warps.
// ---------------------------------------------------------------------------
__global__ __launch_bounds__(320, 2) void gat_prep(const float* __restrict__ h,
                                                   const float* __restrict__ W,
                                                   const float* __restrict__ a,
                                                   const int* __restrict__ adj) {
    extern __shared__ float sA[];
    int t = threadIdx.x;

    if (t >= 256) {
        // ---- pack role (64 threads): adj in {0,1} -> bit = value
        int pt = t - 256;
        size_t wbase = (size_t)blockIdx.x * 2048;
        const int4* adj4 = (const int4*)adj;
#pragma unroll 1
        for (int it = 0; it < 32; it += 2) {
            size_t wi0 = wbase + pt + (size_t)it * 64;
            size_t wi1 = wi0 + 64;
            const int4* s0 = adj4 + wi0 * 8;
            const int4* s1 = adj4 + wi1 * 8;
            int4 v[16];
#pragma unroll
            for (int u = 0; u < 8; u++) v[u] = __ldcs(s0 + u);
#pragma unroll
            for (int u = 0; u < 8; u++) v[8 + u] = __ldcs(s1 + u);
            uint32_t w0 = 0, w1 = 0;
#pragma unroll
            for (int u = 0; u < 8; u++) {
                w0 |= (uint32_t)(v[u].x + 2 * v[u].y + 4 * v[u].z + 8 * v[u].w) << (u * 4);
                w1 |= (uint32_t)(v[8+u].x + 2 * v[8+u].y + 4 * v[8+u].z + 8 * v[8+u].w) << (u * 4);
            }
            g_bits[wi0] = w0;
            g_bits[wi1] = w1;
        }
        return;
    }

    // ---- GEMM role (256 threads)
    unsigned long long* Wp = (unsigned long long*)sA;   // 2048 ull = 16KB
    float* hb = sA + 4096;                              // 2 x (32 rows x 36)
    uint32_t hbase = smem_u32(sA) + 16384;

    int rg = t >> 4, op = t & 15;
    int row0 = blockIdx.x * 32;

    int hr = t >> 3, hf = t & 7;
    const float* hsrc0 = h + (size_t)(row0 + hr) * FIN + hf * 4;

    cpa16(hbase + hr * 144 + hf * 16, hsrc0);             CP_COMMIT();
    cpa16(hbase + 4608 + hr * 144 + hf * 16, hsrc0 + 32); CP_COMMIT();

    unsigned long long acc[2][4];
#pragma unroll
    for (int q = 0; q < 2; q++)
#pragma unroll
        for (int s = 0; s < 4; s++) acc[q][s] = 0ull;

    for (int wq = 0; wq < 4; wq++) {
        BAR_GEMM();
        for (int idx = t; idx < 2048; idx += 256) {
            int kpl = idx >> 6, o = idx & 63;
            int kp = wq * 32 + kpl;
            Wp[idx] = pack2(W[(2 * kp) * FOUT + o], W[(2 * kp + 1) * FOUT + o]);
        }
        for (int kcq = 0; kcq < 2; kcq++) {
            int c = wq * 2 + kcq;
            CP_WAIT1();
            BAR_GEMM();
            const float* hc = hb + (c & 1) * 1152;
#pragma unroll
            for (int kpl = 0; kpl < 16; kpl++) {
                const ulonglong2* wrow = (const ulonglong2*)(Wp + (kcq * 16 + kpl) * 64);
                ulonglong2 wa = wrow[op];
                ulonglong2 wb = wrow[op + 16];
#pragma unroll
                for (int q = 0; q < 2; q++) {
                    unsigned long long hv =
                        *(const unsigned long long*)(hc + (rg * 2 + q) * 36 + 2 * kpl);
                    FMA2(acc[q][0], hv, wa.x);
                    FMA2(acc[q][1], hv, wa.y);
                    FMA2(acc[q][2], hv, wb.x);
                    FMA2(acc[q][3], hv, wb.y);
                }
            }
            BAR_GEMM();
            if (c + 2 < 8)
                cpa16(hbase + (c & 1) * 4608 + hr * 144 + hf * 16, hsrc0 + (c + 2) * 32);
            CP_COMMIT();
        }
    }

    int ov[4] = {2 * op, 2 * op + 1, 2 * op + 32, 2 * op + 33};
    float a1v[4], a2v[4];
#pragma unroll
    for (int s = 0; s < 4; s++) { a1v[s] = a[ov[s]]; a2v[s] = a[FOUT + ov[s]]; }

#pragma unroll
    for (int q = 0; q < 2; q++) {
        int grow = row0 + rg * 2 + q;
        int b = grow >> 11, n = grow & (N_ - 1);
        float vals[4], v1 = 0.f, v2 = 0.f;
#pragma unroll
        for (int s = 0; s < 4; s++) {
            vals[s] = pair_sum(acc[q][s]);
            v1 += vals[s] * a1v[s];
            v2 += vals[s] * a2v[s];
        }
        size_t base = ((size_t)b * 256 + (n >> 3)) * 512 + (n & 7);
#pragma unroll
        for (int s = 0; s < 4; s++)
            g_WhB[base + (size_t)ov[s] * 8] = __uint_as_float(tf32u(vals[s]));
#pragma unroll
        for (int off = 1; off < 16; off <<= 1) {
            v1 += __shfl_xor_sync(0xffffffffu, v1, off);
            v2 += __shfl_xor_sync(0xffffffffu, v2, off);
        }
        if (op == 0) {
            float s = v1 * LOG2E, d = v2 * LOG2E;
            g_esrc[grow] = s;
            g_edEF[grow] = make_float2(ex2f(d), ex2f(0.2f * d));
        }
    }
}

// ---------------------------------------------------------------------------
// Kernel B: bitmask + factored-exp attention -> mma.sync tf32 P @ Wh.
// Grid (32,8)=256 blocks x 256 threads, 2 blocks/SM.
// Warp w: rh=w&1 (rows rh*32..+31), jq=w>>1 (j-quarter of 512).
// Warp PAIR owns a private 3-buffer slice, synced by named barrier (64 thr).
// p = bit ? max(Ei*Ej, Fi*Fj) : 0 (== exp2(leaky)), tf32.
// Rowsum via ones-B MMA (same tf32 p as numerator -> exact normalization).
// ---------------------------------------------------------------------------
#define SLICE_SZ 8448                      // 8192 Wh + 256 EF
#define SM_TOTB  (4 * 3 * SLICE_SZ)        // 101376

__device__ __forceinline__ void pf_slice(uint32_t dst, const char* whsrc,
                                         const float2* efsrc, int jq, int cc, int lt) {
    const char* wsrc = whsrc + (size_t)(jq * 64 + cc * 4) * 2048;
#pragma unroll
    for (int i = 0; i < 8; i++)
        cpa16(dst + (lt + 64 * i) * 16, wsrc + (size_t)(lt + 64 * i) * 16);
    if (lt < 16)
        cpa16(dst + 8192 + lt * 16,
              (const char*)(efsrc + (size_t)jq * 512 + cc * 32) + lt * 16);
}

__global__ __launch_bounds__(256, 2) void gat_attn(float* __restrict__ out) {
    extern __shared__ char sm[];
    uint32_t smb = smem_u32(sm);

    int t = threadIdx.x;
    int w = t >> 5, lane = t & 31;
    int q = lane >> 2, c = lane & 3;
    int b = blockIdx.y;
    int i0 = blockIdx.x * 64;
    int rowbase = b * N_;
    int rh = w & 1, jq = w >> 1;
    int wr = rh * 32;
    int lt = t & 63;
    uint32_t slice0 = smb + jq * 3 * SLICE_SZ;

    const char*   whsrc = (const char*)(g_WhB + (size_t)b * N_ * FOUT);
    const float2* efsrc = g_edEF + rowbase;

    float Ei[4], Fi[4];
#pragma unroll
    for (int r = 0; r < 4; r++) {
        float si = g_esrc[rowbase + i0 + wr + q + 8 * r];
        Ei[r] = ex2f(si);
        Fi[r] = ex2f(0.2f * si);
    }

    const uint32_t* bitsb = g_bits + (size_t)(rowbase + i0 + wr + q) * 64 + jq * 16;

    pf_slice(slice0, whsrc, efsrc, jq, 0, lt);            CP_COMMIT();
    pf_slice(slice0 + SLICE_SZ, whsrc, efsrc, jq, 1, lt); CP_COMMIT();

    float acc[2][8][4];
#pragma unroll
    for (int f = 0; f < 2; f++)
#pragma unroll
        for (int nt = 0; nt < 8; nt++)
#pragma unroll
            for (int s = 0; s < 4; s++) acc[f][nt][s] = 0.f;
    float acc_rs[2][4];
#pragma unroll
    for (int f = 0; f < 2; f++)
#pragma unroll
        for (int s = 0; s < 4; s++) acc_rs[f][s] = 0.f;

#pragma unroll 1
    for (int cc = 0; cc < 16; cc++) {
        uint32_t wbits[4];
#pragma unroll
        for (int r = 0; r < 4; r++)
            wbits[r] = __ldg(bitsb + (size_t)(8 * r) * 64 + cc);

        CP_WAIT1();
        BAR_PAIR(jq + 1);
        if (cc + 2 < 16)
            pf_slice(slice0 + ((cc + 2) % 3) * SLICE_SZ, whsrc, efsrc, jq, cc + 2, lt);
        CP_COMMIT();

        const float* Bc = (const float*)(sm + (size_t)(jq * 3 + (cc % 3)) * SLICE_SZ);
        const float* Ec = Bc + 2048;

#pragma unroll
        for (int ks = 0; ks < 4; ks++) {
            float4 ef = *(const float4*)(Ec + (ks * 8 + 2 * c) * 2);
            int sh = ks * 8 + 2 * c;
            uint32_t pa[4][2];
#pragma unroll
            for (int r = 0; r < 4; r++) {
                float p0 = fmaxf(Ei[r] * ef.x, Fi[r] * ef.y);
                float p1 = fmaxf(Ei[r] * ef.z, Fi[r] * ef.w);
                pa[r][0] = ((wbits[r] >> sh) & 1u) ? tf32u(p0) : 0u;
                pa[r][1] = ((wbits[r] >> (sh + 1)) & 1u) ? tf32u(p1) : 0u;
            }
#pragma unroll
            for (int nt = 0; nt < 8; nt++) {
                float2 wv = *(const float2*)(Bc + ks * 512 + (nt * 8 + q) * 8 + 2 * c);
                uint32_t b0 = __float_as_uint(wv.x), b1 = __float_as_uint(wv.y);
                MMA_TF32(acc[0][nt], pa[0][0], pa[1][0], pa[0][1], pa[1][1], b0, b1);
                MMA_TF32(acc[1][nt], pa[2][0], pa[3][0], pa[2][1], pa[3][1], b0, b1);
            }
            // rowsum (B = all ones -> every lane's D holds the row sum)
            MMA_TF32(acc_rs[0], pa[0][0], pa[1][0], pa[0][1], pa[1][1], ONE_TF, ONE_TF);
            MMA_TF32(acc_rs[1], pa[2][0], pa[3][0], pa[2][1], pa[3][1], ONE_TF, ONE_TF);
        }
    }

    // combine 4 j-quarters via smem (reuses staging)
    float* dsm = (float*)sm;                 // [3][64][66]
    float* rsm = (float*)(sm + 50688);       // [3][64]
    __syncthreads();
    if (jq != 0) {
        float* dst = dsm + (jq - 1) * 4224;
#pragma unroll
        for (int f = 0; f < 2; f++) {
            int row0 = wr + 16 * f + q;
#pragma unroll
            for (int nt = 0; nt < 8; nt++) {
                *(float2*)(dst + row0 * 66 + nt * 8 + 2 * c) =
                    make_float2(acc[f][nt][0], acc[f][nt][1]);
                *(float2*)(dst + (row0 + 8) * 66 + nt * 8 + 2 * c) =
                    make_float2(acc[f][nt][2], acc[f][nt][3]);
            }
            if (c == 0) {
                rsm[(jq - 1) * 64 + row0]     = acc_rs[f][0];
                rsm[(jq - 1) * 64 + row0 + 8] = acc_rs[f][2];
            }
        }
    }
    __syncthreads();
    if (jq == 0) {
#pragma unroll
        for (int f = 0; f < 2; f++) {
            int row0 = wr + 16 * f + q;
            float i0v = 1.0f / (acc_rs[f][0] + rsm[row0] + rsm[64 + row0] + rsm[128 + row0]);
            float i1v = 1.0f / (acc_rs[f][2] + rsm[row0 + 8] + rsm[64 + row0 + 8]
                                + rsm[128 + row0 + 8]);
            float* o0 = out + (size_t)(rowbase + i0 + row0) * FOUT;
            float* o1 = out + (size_t)(rowbase + i0 + row0 + 8) * FOUT;
#pragma unroll
            for (int nt = 0; nt < 8; nt++) {
                int col = nt * 8 + 2 * c;
                float s0x = acc[f][nt][0], s0y = acc[f][nt][1];
                float s1x = acc[f][nt][2], s1y = acc[f][nt][3];
#pragma unroll
                for (int p = 0; p < 3; p++) {
                    const float* dp = dsm + p * 4224;
                    float2 d0 = *(const float2*)(dp + row0 * 66 + col);
                    float2 d1 = *(const float2*)(dp + (row0 + 8) * 66 + col);
                    s0x += d0.x; s0y += d0.y;
                    s1x += d1.x; s1y += d1.y;
                }
                float y;
                float2 v0, v1;
                y = s0x * i0v; v0.x = y > 0.f ? y : expm1f(y);
                y = s0y * i0v; v0.y = y > 0.f ? y : expm1f(y);
                y = s1x * i1v; v1.x = y > 0.f ? y : expm1f(y);
                y = s1y * i1v; v1.y = y > 0.f ? y : expm1f(y);
                *(float2*)(o0 + col) = v0;
                *(float2*)(o1 + col) = v1;
            }
        }
    }
}

// ---------------------------------------------------------------------------
extern "C" void kernel_launch(void* const* d_in, const int* in_sizes, int n_in,
                              void* d_out, int out_size) {
    const float* h   = (const float*)d_in[0];
    const int*   adj = (const int*)d_in[1];
    const float* W   = (const float*)d_in[2];
    const float* a   = (const float*)d_in[3];
    float*       out = (float*)d_out;

    const int smemA = (4096 + 2 * 1152) * 4;   // 25.6 KB
    cudaFuncSetAttribute(gat_prep, cudaFuncAttributeMaxDynamicSharedMemorySize, smemA);
    cudaFuncSetAttribute(gat_attn, cudaFuncAttributeMaxDynamicSharedMemorySize, SM_TOTB);

    gat_prep<<<(B_ * N_) / 32, 320, smemA>>>(h, W, a, adj);

    dim3 gridB(N_ / 64, B_);   // (32, 8) = 256 blocks
    gat_attn<<<gridB, 256, SM_TOTB>>>(out);
}

// round 11
// speedup vs baseline: 1.4726x; 1.4726x over previous
#include <cuda_runtime.h>
#include <cstdint>

#define B_     8
#define N_     2048
#define FIN    256
#define FOUT   64
#define LOG2E  1.4426950408889634f
#define ONE_TF 0x3f800000u

// Scratch (device globals: allocation-free rule)
__device__ float    g_WhB[B_ * N_ * FOUT];  // [b][j>>3][o][j&7], tf32-pre-rounded
__device__ float    g_esrc[B_ * N_];        // log2-scaled src logits
__device__ float2   g_edEF[B_ * N_];        // per node: (exp2(d), exp2(0.2 d))

// ---------------------------------------------------------------------------
// helpers
// ---------------------------------------------------------------------------
__device__ __forceinline__ uint32_t smem_u32(const void* p) {
    uint32_t a;
    asm("{ .reg .u64 t; cvta.to.shared.u64 t, %1; cvt.u32.u64 %0, t; }" : "=r"(a) : "l"(p));
    return a;
}
__device__ __forceinline__ void cpa16(uint32_t dst, const void* src) {
    asm volatile("cp.async.cg.shared.global [%0], [%1], 16;" :: "r"(dst), "l"(src));
}
#define CP_COMMIT() asm volatile("cp.async.commit_group;" ::: "memory")
#define CP_WAIT1()  asm volatile("cp.async.wait_group 1;" ::: "memory")
#define BAR_PAIR(id) asm volatile("bar.sync %0, 128;" :: "r"(id) : "memory")

__device__ __forceinline__ float ex2f(float x) {
    float r; asm("ex2.approx.f32 %0, %1;" : "=f"(r) : "f"(x)); return r;
}
__device__ __forceinline__ uint32_t tf32u(float x) {
    uint32_t r; asm("cvt.rn.tf32.f32 %0, %1;" : "=r"(r) : "f"(x)); return r;
}
// D += A*B, m16n8k8 tf32 (base PTX ISA)
#define MMA_TF32(d, a0, a1, a2, a3, b0, b1)                                   \
    asm volatile("mma.sync.aligned.m16n8k8.row.col.f32.tf32.tf32.f32 "        \
                 "{%0,%1,%2,%3}, {%4,%5,%6,%7}, {%8,%9}, {%0,%1,%2,%3};"      \
                 : "+f"((d)[0]), "+f"((d)[1]), "+f"((d)[2]), "+f"((d)[3])     \
                 : "r"(a0), "r"(a1), "r"(a2), "r"(a3), "r"(b0), "r"(b1))

// packed fp32x2 FMA (prep kernel)
#define FMA2(d, a, b) asm("fma.rn.f32x2 %0, %1, %2, %0;" : "+l"(d) : "l"(a), "l"(b))
__device__ __forceinline__ float pair_sum(unsigned long long v) {
    float lo, hi;
    asm("mov.b64 {%0, %1}, %2;" : "=f"(lo), "=f"(hi) : "l"(v));
    return lo + hi;
}
__device__ __forceinline__ unsigned long long pack2(float lo, float hi) {
    unsigned long long r;
    asm("mov.b64 %0, {%1, %2};" : "=l"(r) : "f"(lo), "f"(hi));
    return r;
}

// ---------------------------------------------------------------------------
// Kernel PREP (round-6 structure, 29us measured): Wh = h @ W via FFMA2.
// 512 blocks x 256 threads, 32 rows/block. W staged per 16KB quarter,
// h double-buffered via cp.async. Stores g_WhB (tf32, fragment layout),
// g_esrc (log2-scaled), g_edEF = (exp2(d), exp2(0.2d)). NO adj pack.
// ---------------------------------------------------------------------------
__global__ __launch_bounds__(256) void gat_prep(const float* __restrict__ h,
                                                const float* __restrict__ W,
                                                const float* __restrict__ a) {
    extern __shared__ float sA[];
    unsigned long long* Wp = (unsigned long long*)sA;   // 2048 ull = 16KB
    float* hb = sA + 4096;                              // 2 x (32 rows x 36)
    uint32_t hbase = smem_u32(sA) + 16384;

    int t = threadIdx.x;
    int rg = t >> 4, op = t & 15;
    int row0 = blockIdx.x * 32;

    int hr = t >> 3, hf = t & 7;
    const float* hsrc0 = h + (size_t)(row0 + hr) * FIN + hf * 4;

    cpa16(hbase + hr * 144 + hf * 16, hsrc0);             CP_COMMIT();
    cpa16(hbase + 4608 + hr * 144 + hf * 16, hsrc0 + 32); CP_COMMIT();

    unsigned long long acc[2][4];
#pragma unroll
    for (int q = 0; q < 2; q++)
#pragma unroll
        for (int s = 0; s < 4; s++) acc[q][s] = 0ull;

    for (int wq = 0; wq < 4; wq++) {
        __syncthreads();
        for (int idx = t; idx < 2048; idx += 256) {
            int kpl = idx >> 6, o = idx & 63;
            int kp = wq * 32 + kpl;
            Wp[idx] = pack2(W[(2 * kp) * FOUT + o], W[(2 * kp + 1) * FOUT + o]);
        }
        for (int kcq = 0; kcq < 2; kcq++) {
            int c = wq * 2 + kcq;
            CP_WAIT1();
            __syncthreads();
            const float* hc = hb + (c & 1) * 1152;
#pragma unroll
            for (int kpl = 0; kpl < 16; kpl++) {
                const ulonglong2* wrow = (const ulonglong2*)(Wp + (kcq * 16 + kpl) * 64);
                ulonglong2 wa = wrow[op];
                ulonglong2 wb = wrow[op + 16];
#pragma unroll
                for (int q = 0; q < 2; q++) {
                    unsigned long long hv =
                        *(const unsigned long long*)(hc + (rg * 2 + q) * 36 + 2 * kpl);
                    FMA2(acc[q][0], hv, wa.x);
                    FMA2(acc[q][1], hv, wa.y);
                    FMA2(acc[q][2], hv, wb.x);
                    FMA2(acc[q][3], hv, wb.y);
                }
            }
            __syncthreads();
            if (c + 2 < 8)
                cpa16(hbase + (c & 1) * 4608 + hr * 144 + hf * 16, hsrc0 + (c + 2) * 32);
            CP_COMMIT();
        }
    }

    int ov[4] = {2 * op, 2 * op + 1, 2 * op + 32, 2 * op + 33};
    float a1v[4], a2v[4];
#pragma unroll
    for (int s = 0; s < 4; s++) { a1v[s] = a[ov[s]]; a2v[s] = a[FOUT + ov[s]]; }

#pragma unroll
    for (int q = 0; q < 2; q++) {
        int grow = row0 + rg * 2 + q;
        int b = grow >> 11, n = grow & (N_ - 1);
        float vals[4], v1 = 0.f, v2 = 0.f;
#pragma unroll
        for (int s = 0; s < 4; s++) {
            vals[s] = pair_sum(acc[q][s]);
            v1 += vals[s] * a1v[s];
            v2 += vals[s] * a2v[s];
        }
        size_t base = ((size_t)b * 256 + (n >> 3)) * 512 + (n & 7);
#pragma unroll
        for (int s = 0; s < 4; s++)
            g_WhB[base + (size_t)ov[s] * 8] = __uint_as_float(tf32u(vals[s]));
#pragma unroll
        for (int off = 1; off < 16; off <<= 1) {
            v1 += __shfl_xor_sync(0xffffffffu, v1, off);
            v2 += __shfl_xor_sync(0xffffffffu, v2, off);
        }
        if (op == 0) {
            float s = v1 * LOG2E, d = v2 * LOG2E;
            g_esrc[grow] = s;
            g_edEF[grow] = make_float2(ex2f(d), ex2f(0.2f * d));
        }
    }
}

// ---------------------------------------------------------------------------
// Kernel B: raw-adj streaming attention -> mma.sync tf32 P @ Wh.
// Grid (32,8)=256 blocks x 256 threads, 2 blocks/SM.
// 2 PAIRS of 4 warps: jq = w>>2 (j-half, 1024 j), wp = w&3 (rows wp*16..+15,
// one m16 fragment). 32 chunks of 32 j per half; each chunk's slice holds
// Wh tile (8KB) + RAW adj tile 64x32 int (stride 36, 9KB) + EF (256B),
// triple-buffered cp.async, pair-scoped named barrier (128 thr).
// adj touched exactly once chip-wide (no pre-pack pass).
// p = adj>0 ? max(Ei*Ej, Fi*Fj) : 0 (== exp2(leaky)), tf32.
// Rowsum via ones-B MMA (same tf32 p -> exact normalization).
// ---------------------------------------------------------------------------
#define ADJ_OFF  8192
#define EF_OFF   17408
#define SLICE_SZ 17664                     // 8192 Wh + 9216 adj + 256 EF
#define SM_TOTB  (2 * 3 * SLICE_SZ)        // 105984

__device__ __forceinline__ void pf_slice(uint32_t dst, const char* whsrc,
                                         const char* adjsrc, const float2* efsrc,
                                         int jq, int cc, int lt) {
    // Wh: 8KB contiguous (4 j-groups of 2048B)
    const char* wsrc = whsrc + (size_t)(jq * 128 + cc * 4) * 2048;
#pragma unroll
    for (int i = 0; i < 4; i++)
        cpa16(dst + (lt + 128 * i) * 16, wsrc + (size_t)(lt + 128 * i) * 16);
    // adj: 64 rows x 128B, row stride 8KB in gmem, 144B in smem
#pragma unroll
    for (int i = 0; i < 4; i++) {
        int idx = i * 128 + lt;            // 512 x 16B
        int r = idx >> 3, u = idx & 7;
        cpa16(dst + ADJ_OFF + r * 144 + u * 16,
              adjsrc + ((size_t)r << 13) + (size_t)(jq * 4096 + cc * 128) + u * 16);
    }
    if (lt < 16)
        cpa16(dst + EF_OFF + lt * 16,
              (const char*)(efsrc + (size_t)jq * 1024 + cc * 32) + lt * 16);
}

__global__ __launch_bounds__(256, 2) void gat_attn(const int* __restrict__ adj,
                                                   float* __restrict__ out) {
    extern __shared__ char sm[];
    uint32_t smb = smem_u32(sm);

    int t = threadIdx.x;
    int w = t >> 5, lane = t & 31;
    int q = lane >> 2, c = lane & 3;
    int b = blockIdx.y;
    int i0 = blockIdx.x * 64;
    int rowbase = b * N_;
    int jq = w >> 2, wp = w & 3;
    int lr0 = wp * 16 + q;                 // this lane's two rows (m16)
    int lt = t & 127;
    uint32_t slice0 = smb + jq * 3 * SLICE_SZ;

    const char*   whsrc  = (const char*)(g_WhB + (size_t)b * N_ * FOUT);
    const char*   adjsrc = (const char*)(adj + ((size_t)(rowbase + i0) << 11));
    const float2* efsrc  = g_edEF + rowbase;

    float si0 = g_esrc[rowbase + i0 + lr0];
    float si8 = g_esrc[rowbase + i0 + lr0 + 8];
    float Ei0 = ex2f(si0), Fi0 = ex2f(0.2f * si0);
    float Ei8 = ex2f(si8), Fi8 = ex2f(0.2f * si8);

    pf_slice(slice0, whsrc, adjsrc, efsrc, jq, 0, lt);            CP_COMMIT();
    pf_slice(slice0 + SLICE_SZ, whsrc, adjsrc, efsrc, jq, 1, lt); CP_COMMIT();

    float acc[8][4];
#pragma unroll
    for (int nt = 0; nt < 8; nt++)
#pragma unroll
        for (int s = 0; s < 4; s++) acc[nt][s] = 0.f;
    float acc_rs[4] = {0.f, 0.f, 0.f, 0.f};

#pragma unroll 1
    for (int cc = 0; cc < 32; cc++) {
        CP_WAIT1();
        BAR_PAIR(jq + 1);
        if (cc + 2 < 32)
            pf_slice(slice0 + ((cc + 2) % 3) * SLICE_SZ, whsrc, adjsrc, efsrc,
                     jq, cc + 2, lt);
        CP_COMMIT();

        const char*  Sc = sm + (size_t)(jq * 3 + (cc % 3)) * SLICE_SZ;
        const float* Bc = (const float*)Sc;
        const int*   Ac = (const int*)(Sc + ADJ_OFF);
        const float* Ec = (const float*)(Sc + EF_OFF);

        // hoist this chunk's adj values (2 rows x 4 ks x 2 j)
        int2 A0[4], A8[4];
#pragma unroll
        for (int ks = 0; ks < 4; ks++) {
            A0[ks] = *(const int2*)(Ac + lr0 * 36 + ks * 8 + 2 * c);
            A8[ks] = *(const int2*)(Ac + (lr0 + 8) * 36 + ks * 8 + 2 * c);
        }

#pragma unroll
        for (int ks = 0; ks < 4; ks++) {
            float4 ef = *(const float4*)(Ec + (ks * 8 + 2 * c) * 2);
            uint32_t a0 = A0[ks].x > 0 ? tf32u(fmaxf(Ei0 * ef.x, Fi0 * ef.y)) : 0u;
            uint32_t a1 = A8[ks].x > 0 ? tf32u(fmaxf(Ei8 * ef.x, Fi8 * ef.y)) : 0u;
            uint32_t a2 = A0[ks].y > 0 ? tf32u(fmaxf(Ei0 * ef.z, Fi0 * ef.w)) : 0u;
            uint32_t a3 = A8[ks].y > 0 ? tf32u(fmaxf(Ei8 * ef.z, Fi8 * ef.w)) : 0u;
#pragma unroll
            for (int nt = 0; nt < 8; nt++) {
                float2 wv = *(const float2*)(Bc + ks * 512 + (nt * 8 + q) * 8 + 2 * c);
                MMA_TF32(acc[nt], a0, a1, a2, a3,
                         __float_as_uint(wv.x), __float_as_uint(wv.y));
            }
            MMA_TF32(acc_rs, a0, a1, a2, a3, ONE_TF, ONE_TF);
        }
    }

    // combine the 2 j-halves via smem (reuses staging)
    float* dsm = (float*)sm;                 // [64][66]
    float* rsm = (float*)(sm + 16896);       // [64]
    __syncthreads();
    if (jq == 1) {
#pragma unroll
        for (int nt = 0; nt < 8; nt++) {
            *(float2*)(dsm + lr0 * 66 + nt * 8 + 2 * c) =
                make_float2(acc[nt][0], acc[nt][1]);
            *(float2*)(dsm + (lr0 + 8) * 66 + nt * 8 + 2 * c) =
                make_float2(acc[nt][2], acc[nt][3]);
        }
        if (c == 0) {
            rsm[lr0]     = acc_rs[0];
            rsm[lr0 + 8] = acc_rs[2];
        }
    }
    __syncthreads();
    if (jq == 0) {
        float i0v = 1.0f / (acc_rs[0] + rsm[lr0]);
        float i8v = 1.0f / (acc_rs[2] + rsm[lr0 + 8]);
        float* o0 = out + (size_t)(rowbase + i0 + lr0) * FOUT;
        float* o8 = out + (size_t)(rowbase + i0 + lr0 + 8) * FOUT;
#pragma unroll
        for (int nt = 0; nt < 8; nt++) {
            int col = nt * 8 + 2 * c;
            float2 d0 = *(const float2*)(dsm + lr0 * 66 + col);
            float2 d8 = *(const float2*)(dsm + (lr0 + 8) * 66 + col);
            float y;
            float2 v0, v8;
            y = (acc[nt][0] + d0.x) * i0v; v0.x = y > 0.f ? y : expm1f(y);
            y = (acc[nt][1] + d0.y) * i0v; v0.y = y > 0.f ? y : expm1f(y);
            y = (acc[nt][2] + d8.x) * i8v; v8.x = y > 0.f ? y : expm1f(y);
            y = (acc[nt][3] + d8.y) * i8v; v8.y = y > 0.f ? y : expm1f(y);
            *(float2*)(o0 + col) = v0;
            *(float2*)(o8 + col) = v8;
        }
    }
}

// ---------------------------------------------------------------------------
extern "C" void kernel_launch(void* const* d_in, const int* in_sizes, int n_in,
                              void* d_out, int out_size) {
    const float* h   = (const float*)d_in[0];
    const int*   adj = (const int*)d_in[1];
    const float* W   = (const float*)d_in[2];
    const float* a   = (const float*)d_in[3];
    float*       out = (float*)d_out;

    const int smemA = (4096 + 2 * 1152) * 4;   // 25.6 KB
    cudaFuncSetAttribute(gat_prep, cudaFuncAttributeMaxDynamicSharedMemorySize, smemA);
    cudaFuncSetAttribute(gat_attn, cudaFuncAttributeMaxDynamicSharedMemorySize, SM_TOTB);

    gat_prep<<<(B_ * N_) / 32, 256, smemA>>>(h, W, a);

    dim3 gridB(N_ / 64, B_);   // (32, 8) = 256 blocks
    gat_attn<<<gridB, 256, SM_TOTB>>>(adj, out);
}